// round 1
// baseline (speedup 1.0000x reference)
#include <cuda_runtime.h>
#include <math.h>

// ============================================================================
// MultiHeadAttention: out = softmax((XqWq)(XkWk)^T / sqrt(Hd)) (XvWv)
// B=8, S=1024, D=1024, H=16, Hd=64. All fp32.
//
// Round-0 baseline: fp32 FFMA SGEMM projections + fused fp32 flash attention.
// Scratch for projected Q/K/V lives in __device__ globals (no allocations).
// ============================================================================

#define MHA_M   8192     // B*S
#define MHA_D   1024
#define MHA_H   16
#define MHA_HD  64
#define MHA_S   1024
#define MHA_B   8

__device__ float g_Qp[MHA_M * MHA_D];
__device__ float g_Kp[MHA_M * MHA_D];
__device__ float g_Vp[MHA_M * MHA_D];

// ----------------------------------------------------------------------------
// SGEMM: C[M,N] = A[M,K] @ B[K,N], fp32, 128x128x8 tiles, 256 threads, 8x8/thr
// ----------------------------------------------------------------------------
#define GEMM_BM 128
#define GEMM_BN 128
#define GEMM_BK 8

__global__ __launch_bounds__(256, 2)
void sgemm128(const float* __restrict__ A, const float* __restrict__ B,
              float* __restrict__ C, int M, int N, int K)
{
    __shared__ float As[2][GEMM_BK][GEMM_BM];   // transposed: As[k][m]
    __shared__ float Bs[2][GEMM_BK][GEMM_BN];   // Bs[k][n]

    const int tid = threadIdx.x;
    const int m0 = blockIdx.y * GEMM_BM;
    const int n0 = blockIdx.x * GEMM_BN;

    const int arow = tid >> 1;          // 0..127
    const int acol = (tid & 1) << 2;    // 0 or 4
    const int brow = tid >> 5;          // 0..7
    const int bcol = (tid & 31) << 2;   // 0..124

    const int ty = tid >> 4;            // 0..15
    const int tx = tid & 15;            // 0..15

    const float* Aptr = A + (size_t)(m0 + arow) * K + acol;
    const float* Bptr = B + (size_t)brow * N + n0 + bcol;

    float acc[8][8];
#pragma unroll
    for (int i = 0; i < 8; ++i)
#pragma unroll
        for (int j = 0; j < 8; ++j) acc[i][j] = 0.f;

    // preload tile 0
    float4 ar = *(const float4*)Aptr;
    float4 br = *(const float4*)Bptr;
    As[0][acol + 0][arow] = ar.x;
    As[0][acol + 1][arow] = ar.y;
    As[0][acol + 2][arow] = ar.z;
    As[0][acol + 3][arow] = ar.w;
    *(float4*)&Bs[0][brow][bcol] = br;
    __syncthreads();

    const int T = K / GEMM_BK;
    for (int t = 0; t < T; ++t) {
        const int cur = t & 1;
        if (t + 1 < T) {
            ar = *(const float4*)(Aptr + (t + 1) * GEMM_BK);
            br = *(const float4*)(Bptr + (size_t)(t + 1) * GEMM_BK * N);
        }
#pragma unroll
        for (int k = 0; k < GEMM_BK; ++k) {
            float4 a0 = *(const float4*)&As[cur][k][ty * 4];
            float4 a1 = *(const float4*)&As[cur][k][64 + ty * 4];
            float4 b0 = *(const float4*)&Bs[cur][k][tx * 4];
            float4 b1 = *(const float4*)&Bs[cur][k][64 + tx * 4];
            float av[8] = {a0.x, a0.y, a0.z, a0.w, a1.x, a1.y, a1.z, a1.w};
            float bv[8] = {b0.x, b0.y, b0.z, b0.w, b1.x, b1.y, b1.z, b1.w};
#pragma unroll
            for (int i = 0; i < 8; ++i)
#pragma unroll
                for (int j = 0; j < 8; ++j)
                    acc[i][j] = fmaf(av[i], bv[j], acc[i][j]);
        }
        if (t + 1 < T) {
            const int nxt = cur ^ 1;
            As[nxt][acol + 0][arow] = ar.x;
            As[nxt][acol + 1][arow] = ar.y;
            As[nxt][acol + 2][arow] = ar.z;
            As[nxt][acol + 3][arow] = ar.w;
            *(float4*)&Bs[nxt][brow][bcol] = br;
            __syncthreads();
        }
    }

#pragma unroll
    for (int i = 0; i < 8; ++i) {
        const int m = m0 + ((i < 4) ? (ty * 4 + i) : (64 + ty * 4 + i - 4));
        float4 c0 = make_float4(acc[i][0], acc[i][1], acc[i][2], acc[i][3]);
        float4 c1 = make_float4(acc[i][4], acc[i][5], acc[i][6], acc[i][7]);
        *(float4*)&C[(size_t)m * N + n0 + tx * 4]      = c0;
        *(float4*)&C[(size_t)m * N + n0 + 64 + tx * 4] = c1;
    }
}

// ----------------------------------------------------------------------------
// Flash attention, fp32. One CTA = 64 Q rows of one (b,h). 256 threads.
// Layouts: Q/K/V projected buffers are [B*S][H*Hd]; per-(b,h) rows strided by D.
// Q is pre-scaled by (1/sqrt(Hd)) * log2(e) so softmax uses exp2.
// ----------------------------------------------------------------------------
#define FA_BR  64
#define FA_BC  64
#define FA_HD  64
#define FA_LDP 68   // padded row stride (floats); 68*4 bytes keeps float4 align

#define FA_SMEM_FLOATS (3 * FA_HD * FA_LDP + FA_BC * FA_HD)
#define FA_SMEM_BYTES  (FA_SMEM_FLOATS * 4)

__global__ __launch_bounds__(256, 2)
void flash_attn(const float* __restrict__ Qp, const float* __restrict__ Kp,
                const float* __restrict__ Vp, float* __restrict__ Out,
                int S, int H)
{
    extern __shared__ float sm[];
    float* Qt = sm;                         // [HD][LDP]  Qt[d][i]
    float* Kt = Qt + FA_HD * FA_LDP;        // [HD][LDP]  Kt[d][j]
    float* Pt = Kt + FA_HD * FA_LDP;        // [BC][LDP]  Pt[j][i]
    float* Vs = Pt + FA_BC * FA_LDP;        // [BC][HD]   Vs[j][d]

    const int tid = threadIdx.x;
    const int ty = tid >> 4;                // 0..15 -> row group
    const int tx = tid & 15;                // 0..15 -> col group
    const int D = H * FA_HD;

    const int qblk = blockIdx.x;
    const int bh = blockIdx.y;
    const int b = bh / H;
    const int h = bh % H;

    const float* Qbase = Qp + (size_t)(b * S + qblk * FA_BR) * D + h * FA_HD;
    const float* Kbase = Kp + (size_t)(b * S) * D + h * FA_HD;
    const float* Vbase = Vp + (size_t)(b * S) * D + h * FA_HD;

    const float qscale = 0.125f * 1.4426950408889634f;  // 1/sqrt(64) * log2(e)

    // Load Q tile transposed + scaled (once per CTA).
    {
        const int row = tid >> 2;           // 0..63
        const int c0 = (tid & 3) << 4;      // 0,16,32,48
#pragma unroll
        for (int u = 0; u < 4; ++u) {
            float4 v = *(const float4*)(Qbase + (size_t)row * D + c0 + 4 * u);
            Qt[(c0 + 4 * u + 0) * FA_LDP + row] = v.x * qscale;
            Qt[(c0 + 4 * u + 1) * FA_LDP + row] = v.y * qscale;
            Qt[(c0 + 4 * u + 2) * FA_LDP + row] = v.z * qscale;
            Qt[(c0 + 4 * u + 3) * FA_LDP + row] = v.w * qscale;
        }
    }

    float m_i[4], l_i[4], o[4][4];
#pragma unroll
    for (int r = 0; r < 4; ++r) {
        m_i[r] = -1e30f;
        l_i[r] = 0.f;
#pragma unroll
        for (int c = 0; c < 4; ++c) o[r][c] = 0.f;
    }

    const int nkv = S / FA_BC;
    for (int kv = 0; kv < nkv; ++kv) {
        __syncthreads();  // prior iter done reading Kt/Vs/Pt; Qt visible (iter 0)

        // Load K tile transposed, V tile direct.
        {
            const int row = tid >> 2;
            const int c0 = (tid & 3) << 4;
            const float* kp = Kbase + (size_t)(kv * FA_BC + row) * D + c0;
            const float* vp = Vbase + (size_t)(kv * FA_BC + row) * D + c0;
#pragma unroll
            for (int u = 0; u < 4; ++u) {
                float4 kk = *(const float4*)(kp + 4 * u);
                Kt[(c0 + 4 * u + 0) * FA_LDP + row] = kk.x;
                Kt[(c0 + 4 * u + 1) * FA_LDP + row] = kk.y;
                Kt[(c0 + 4 * u + 2) * FA_LDP + row] = kk.z;
                Kt[(c0 + 4 * u + 3) * FA_LDP + row] = kk.w;
                *(float4*)&Vs[row * FA_HD + c0 + 4 * u] = *(const float4*)(vp + 4 * u);
            }
        }
        __syncthreads();

        // S tile: s[r][c] = sum_d Q[i][d]*K[j][d], i=ty*4+r, j=tx*4+c
        float s[4][4];
#pragma unroll
        for (int r = 0; r < 4; ++r)
#pragma unroll
            for (int c = 0; c < 4; ++c) s[r][c] = 0.f;

#pragma unroll 8
        for (int d = 0; d < FA_HD; ++d) {
            float4 qv = *(const float4*)&Qt[d * FA_LDP + ty * 4];
            float4 kvv = *(const float4*)&Kt[d * FA_LDP + tx * 4];
            float qa[4] = {qv.x, qv.y, qv.z, qv.w};
            float ka[4] = {kvv.x, kvv.y, kvv.z, kvv.w};
#pragma unroll
            for (int r = 0; r < 4; ++r)
#pragma unroll
                for (int c = 0; c < 4; ++c)
                    s[r][c] = fmaf(qa[r], ka[c], s[r][c]);
        }

        // Online softmax (scores already in log2 domain).
#pragma unroll
        for (int r = 0; r < 4; ++r) {
            float rm = fmaxf(fmaxf(s[r][0], s[r][1]), fmaxf(s[r][2], s[r][3]));
#pragma unroll
            for (int msk = 8; msk; msk >>= 1)
                rm = fmaxf(rm, __shfl_xor_sync(0xffffffffu, rm, msk));
            const float mnew = fmaxf(m_i[r], rm);
            const float alpha = exp2f(m_i[r] - mnew);
            float rs = 0.f;
#pragma unroll
            for (int c = 0; c < 4; ++c) {
                float p = exp2f(s[r][c] - mnew);
                s[r][c] = p;
                rs += p;
            }
#pragma unroll
            for (int msk = 8; msk; msk >>= 1)
                rs += __shfl_xor_sync(0xffffffffu, rs, msk);
            l_i[r] = l_i[r] * alpha + rs;
            m_i[r] = mnew;
#pragma unroll
            for (int c = 0; c < 4; ++c) o[r][c] *= alpha;
        }

        // Stage P transposed: Pt[j][i]
#pragma unroll
        for (int r = 0; r < 4; ++r)
#pragma unroll
            for (int c = 0; c < 4; ++c)
                Pt[(tx * 4 + c) * FA_LDP + (ty * 4 + r)] = s[r][c];
        __syncthreads();

        // O += P @ V : o[r][c] over i=ty*4+r, d=tx*4+c
#pragma unroll 8
        for (int j = 0; j < FA_BC; ++j) {
            float4 pv = *(const float4*)&Pt[j * FA_LDP + ty * 4];
            float4 vv = *(const float4*)&Vs[j * FA_HD + tx * 4];
            float pa[4] = {pv.x, pv.y, pv.z, pv.w};
            float va[4] = {vv.x, vv.y, vv.z, vv.w};
#pragma unroll
            for (int r = 0; r < 4; ++r)
#pragma unroll
                for (int c = 0; c < 4; ++c)
                    o[r][c] = fmaf(pa[r], va[c], o[r][c]);
        }
    }

    // Epilogue: normalize and write [B,S,H*Hd]
#pragma unroll
    for (int r = 0; r < 4; ++r) {
        const float inv = 1.f / l_i[r];
        float4 ov = make_float4(o[r][0] * inv, o[r][1] * inv,
                                o[r][2] * inv, o[r][3] * inv);
        *(float4*)&Out[(size_t)(b * S + qblk * FA_BR + ty * 4 + r) * D
                       + h * FA_HD + tx * 4] = ov;
    }
}

// ----------------------------------------------------------------------------
// Launch
// ----------------------------------------------------------------------------
extern "C" void kernel_launch(void* const* d_in, const int* in_sizes, int n_in,
                              void* d_out, int out_size)
{
    const float* q  = (const float*)d_in[0];
    const float* k  = (const float*)d_in[1];
    const float* v  = (const float*)d_in[2];
    const float* Wq = (const float*)d_in[3];
    const float* Wk = (const float*)d_in[4];
    const float* Wv = (const float*)d_in[5];
    float* out = (float*)d_out;

    const int D = MHA_D;
    const int M = in_sizes[0] / D;      // B*S = 8192
    const int S = MHA_S;
    const int B = M / S;
    const int H = MHA_H;

    float *Qb, *Kb, *Vb;
    cudaGetSymbolAddress((void**)&Qb, g_Qp);
    cudaGetSymbolAddress((void**)&Kb, g_Kp);
    cudaGetSymbolAddress((void**)&Vb, g_Vp);

    dim3 gg(D / GEMM_BN, M / GEMM_BM);  // (8, 64)
    sgemm128<<<gg, 256>>>(q, Wq, Qb, M, D, D);
    sgemm128<<<gg, 256>>>(k, Wk, Kb, M, D, D);
    sgemm128<<<gg, 256>>>(v, Wv, Vb, M, D, D);

    cudaFuncSetAttribute(flash_attn, cudaFuncAttributeMaxDynamicSharedMemorySize,
                         FA_SMEM_BYTES);
    dim3 fg(S / FA_BR, B * H);          // (16, 128)
    flash_attn<<<fg, 256, FA_SMEM_BYTES>>>(Qb, Kb, Vb, out, S, H);
}

// round 4
// speedup vs baseline: 1.3704x; 1.3704x over previous
#include <cuda_runtime.h>
#include <cuda_bf16.h>
#include <math.h>
#include <cstdint>

// ============================================================================
// MHA: out = softmax((XqWq)(XkWk)^T / sqrt(Hd)) (XvWv)
// B=8, S=1024, D=1024, H=16, Hd=64, fp32 in/out.
//
// Round 4: target is plain sm_100 (no tcgen05!). Projections use classic
// mma.sync.m16n8k16 bf16 with hi/lo split precision (3 MMAs), fp32 accum.
// Flash attention unchanged (fp32 FFMA).
// ============================================================================

#define MHA_M   8192
#define MHA_D   1024
#define MHA_H   16
#define MHA_HD  64
#define MHA_S   1024

__device__ float g_Qp[MHA_M * MHA_D];
__device__ float g_Kp[MHA_M * MHA_D];
__device__ float g_Vp[MHA_M * MHA_D];
__device__ __nv_bfloat16 g_Ahi[MHA_M * MHA_D];
__device__ __nv_bfloat16 g_Alo[MHA_M * MHA_D];
__device__ __nv_bfloat16 g_Bhi[MHA_D * MHA_D];   // W^T, [N][K]
__device__ __nv_bfloat16 g_Blo[MHA_D * MHA_D];

// ---------------------------------------------------------------------------
// helpers
// ---------------------------------------------------------------------------
__device__ __forceinline__ uint32_t smem_to_u32(const void* p) {
    uint32_t a;
    asm("{ .reg .u64 t; cvta.to.shared.u64 t, %1; cvt.u32.u64 %0, t; }"
        : "=r"(a) : "l"(p));
    return a;
}
__device__ __forceinline__ void ldm4(uint32_t* r, uint32_t addr) {
    asm volatile("ldmatrix.sync.aligned.m8n8.x4.shared.b16 {%0,%1,%2,%3}, [%4];"
                 : "=r"(r[0]), "=r"(r[1]), "=r"(r[2]), "=r"(r[3]) : "r"(addr));
}
__device__ __forceinline__ void mma_bf16(float* d, const uint32_t* a,
                                         const uint32_t* b) {
    asm volatile(
        "mma.sync.aligned.m16n8k16.row.col.f32.bf16.bf16.f32 "
        "{%0,%1,%2,%3}, {%4,%5,%6,%7}, {%8,%9}, {%0,%1,%2,%3};"
        : "+f"(d[0]), "+f"(d[1]), "+f"(d[2]), "+f"(d[3])
        : "r"(a[0]), "r"(a[1]), "r"(a[2]), "r"(a[3]), "r"(b[0]), "r"(b[1]));
}

// ---------------------------------------------------------------------------
// fp32 -> bf16 hi/lo split
// ---------------------------------------------------------------------------
__global__ void convert_split(const float* __restrict__ X,
                              __nv_bfloat16* __restrict__ hi,
                              __nv_bfloat16* __restrict__ lo, int n)
{
    int i = (blockIdx.x * blockDim.x + threadIdx.x) * 4;
    if (i >= n) return;
    float4 v = *(const float4*)(X + i);
    __nv_bfloat16 h0 = __float2bfloat16(v.x);
    __nv_bfloat16 h1 = __float2bfloat16(v.y);
    __nv_bfloat16 h2 = __float2bfloat16(v.z);
    __nv_bfloat16 h3 = __float2bfloat16(v.w);
    __nv_bfloat16 l0 = __float2bfloat16(v.x - __bfloat162float(h0));
    __nv_bfloat16 l1 = __float2bfloat16(v.y - __bfloat162float(h1));
    __nv_bfloat16 l2 = __float2bfloat16(v.z - __bfloat162float(h2));
    __nv_bfloat16 l3 = __float2bfloat16(v.w - __bfloat162float(h3));
    *(__nv_bfloat162*)(hi + i)     = __nv_bfloat162(h0, h1);
    *(__nv_bfloat162*)(hi + i + 2) = __nv_bfloat162(h2, h3);
    *(__nv_bfloat162*)(lo + i)     = __nv_bfloat162(l0, l1);
    *(__nv_bfloat162*)(lo + i + 2) = __nv_bfloat162(l2, l3);
}

// W [K,N] fp32 -> W^T [N,K] bf16 hi/lo
__global__ void transpose_split(const float* __restrict__ W,
                                __nv_bfloat16* __restrict__ hi,
                                __nv_bfloat16* __restrict__ lo, int Dm)
{
    __shared__ float t[32][33];
    const int bx = blockIdx.x * 32;   // n
    const int by = blockIdx.y * 32;   // k
    const int x = threadIdx.x, y = threadIdx.y;
#pragma unroll
    for (int j = 0; j < 4; ++j)
        t[y + 8 * j][x] = W[(size_t)(by + y + 8 * j) * Dm + bx + x];
    __syncthreads();
#pragma unroll
    for (int j = 0; j < 4; ++j) {
        float v = t[x][y + 8 * j];
        __nv_bfloat16 h = __float2bfloat16(v);
        __nv_bfloat16 l = __float2bfloat16(v - __bfloat162float(h));
        size_t o = (size_t)(bx + y + 8 * j) * Dm + by + x;
        hi[o] = h;
        lo[o] = l;
    }
}

// ---------------------------------------------------------------------------
// mma.sync bf16x2-split GEMM.
// C[M,N] tile 128x128, BK=32, 256 threads (8 warps, 4x2), warp tile 32x64.
// C[m,n] = sum_k A[m,k]*B[n,k], A = Ahi+Alo, B = Bhi+Blo (drop lo*lo).
//
// Smem layout per operand-half: 2 kf-slabs (kf = 16-wide K fragment), each
// 128 rows x 48 bytes (16 bf16 data + 8 pad). 48B stride -> ldmatrix phases
// (8 rows) hit 8 distinct 16B segments: conflict-free, no swizzle needed.
// ---------------------------------------------------------------------------
#define G_BM 128
#define G_BN 128
#define G_BK 32
#define G_ROWB  48
#define G_SLAB  (128 * G_ROWB)          // 6144
#define G_T_AHI 0
#define G_T_ALO (2 * G_SLAB)            // 12288
#define G_T_BHI (4 * G_SLAB)            // 24576
#define G_T_BLO (6 * G_SLAB)            // 36864
#define G_STAGE (8 * G_SLAB)            // 49152
#define GEMM_SMEM (2 * G_STAGE)         // 98304

__global__ __launch_bounds__(256, 1)
void gemm_mma_bf16x2(const __nv_bfloat16* __restrict__ Ahi,
                     const __nv_bfloat16* __restrict__ Alo,
                     const __nv_bfloat16* __restrict__ Bhi,
                     const __nv_bfloat16* __restrict__ Blo,
                     float* __restrict__ C, int K, int Nout)
{
    extern __shared__ char smem[];
    const uint32_t smem_base = smem_to_u32(smem);
    const int tid = threadIdx.x;
    const int lane = tid & 31;
    const int wid = tid >> 5;
    const int warp_row = wid >> 1;      // 0..3 (M)
    const int warp_col = wid & 1;       // 0..1 (N)
    const int m0 = blockIdx.y * G_BM;
    const int n0 = blockIdx.x * G_BN;

    // ---- global->smem mapping: 512 16B-chunks per tile, 2 per thread ----
    // chunk = i*256 + tid ; row = chunk>>2 ; c = chunk&3 (c*8 bf16 in row)
    // smem: kf = c>>1, seg = c&1 : slab + row*48 + seg*16
    int rowA[2], cA[2];
    uint32_t sOffT[2];                  // offset within a tile (hi or lo)
#pragma unroll
    for (int i = 0; i < 2; ++i) {
        int chunk = i * 256 + tid;
        rowA[i] = chunk >> 2;
        cA[i] = chunk & 3;
        sOffT[i] = (uint32_t)((cA[i] >> 1) * G_SLAB + rowA[i] * G_ROWB +
                              (cA[i] & 1) * 16);
    }

    // ---- ldmatrix per-lane base offsets (within a kf-slab) ----
    const uint32_t aLM = (uint32_t)((warp_row * 32 + (lane & 15)) * G_ROWB +
                                    (lane >> 4) * 16);
    const uint32_t bLM = (uint32_t)((warp_col * 64 + ((lane >> 4) << 3) +
                                     (lane & 7)) * G_ROWB +
                                    ((lane >> 3) & 1) * 16);

    float acc[2][8][4];
#pragma unroll
    for (int mf = 0; mf < 2; ++mf)
#pragma unroll
        for (int nf = 0; nf < 8; ++nf)
#pragma unroll
            for (int q = 0; q < 4; ++q) acc[mf][nf][q] = 0.f;

    // ---- preload stage 0 ----
    {
#pragma unroll
        for (int i = 0; i < 2; ++i) {
            const size_t ga = (size_t)(m0 + rowA[i]) * K + cA[i] * 8;
            const size_t gb = (size_t)(n0 + rowA[i]) * K + cA[i] * 8;
            *(uint4*)(smem + G_T_AHI + sOffT[i]) = *(const uint4*)(Ahi + ga);
            *(uint4*)(smem + G_T_ALO + sOffT[i]) = *(const uint4*)(Alo + ga);
            *(uint4*)(smem + G_T_BHI + sOffT[i]) = *(const uint4*)(Bhi + gb);
            *(uint4*)(smem + G_T_BLO + sOffT[i]) = *(const uint4*)(Blo + gb);
        }
    }
    __syncthreads();

    const int T = K / G_BK;   // 32
    for (int t = 0; t < T; ++t) {
        const int cur = t & 1;

        // prefetch next stage into registers
        uint4 pf[8];
        if (t + 1 < T) {
            const int k0 = (t + 1) * G_BK;
#pragma unroll
            for (int i = 0; i < 2; ++i) {
                const size_t ga = (size_t)(m0 + rowA[i]) * K + k0 + cA[i] * 8;
                const size_t gb = (size_t)(n0 + rowA[i]) * K + k0 + cA[i] * 8;
                pf[i * 4 + 0] = *(const uint4*)(Ahi + ga);
                pf[i * 4 + 1] = *(const uint4*)(Alo + ga);
                pf[i * 4 + 2] = *(const uint4*)(Bhi + gb);
                pf[i * 4 + 3] = *(const uint4*)(Blo + gb);
            }
        }

        const uint32_t sb = smem_base + cur * G_STAGE;
#pragma unroll
        for (int kf = 0; kf < 2; ++kf) {
            const uint32_t kfo = kf * G_SLAB;
            uint32_t ah[2][4], al[2][4], bh[8][2], bl[8][2];
#pragma unroll
            for (int mf = 0; mf < 2; ++mf) {
                ldm4(ah[mf], sb + G_T_AHI + kfo + aLM + mf * 16 * G_ROWB);
                ldm4(al[mf], sb + G_T_ALO + kfo + aLM + mf * 16 * G_ROWB);
            }
#pragma unroll
            for (int pr = 0; pr < 4; ++pr) {
                uint32_t r[4];
                ldm4(r, sb + G_T_BHI + kfo + bLM + pr * 16 * G_ROWB);
                bh[pr * 2][0] = r[0]; bh[pr * 2][1] = r[1];
                bh[pr * 2 + 1][0] = r[2]; bh[pr * 2 + 1][1] = r[3];
                ldm4(r, sb + G_T_BLO + kfo + bLM + pr * 16 * G_ROWB);
                bl[pr * 2][0] = r[0]; bl[pr * 2][1] = r[1];
                bl[pr * 2 + 1][0] = r[2]; bl[pr * 2 + 1][1] = r[3];
            }
#pragma unroll
            for (int mf = 0; mf < 2; ++mf)
#pragma unroll
                for (int nf = 0; nf < 8; ++nf) {
                    mma_bf16(acc[mf][nf], ah[mf], bh[nf]);
                    mma_bf16(acc[mf][nf], ah[mf], bl[nf]);
                    mma_bf16(acc[mf][nf], al[mf], bh[nf]);
                }
        }

        if (t + 1 < T) {
            char* sn = smem + (cur ^ 1) * G_STAGE;
#pragma unroll
            for (int i = 0; i < 2; ++i) {
                *(uint4*)(sn + G_T_AHI + sOffT[i]) = pf[i * 4 + 0];
                *(uint4*)(sn + G_T_ALO + sOffT[i]) = pf[i * 4 + 1];
                *(uint4*)(sn + G_T_BHI + sOffT[i]) = pf[i * 4 + 2];
                *(uint4*)(sn + G_T_BLO + sOffT[i]) = pf[i * 4 + 3];
            }
        }
        __syncthreads();
    }

    // ---- epilogue: m16n8 fragment -> C ----
    const int mBase = m0 + warp_row * 32 + (lane >> 2);
    const int nBase = n0 + warp_col * 64 + (lane & 3) * 2;
#pragma unroll
    for (int mf = 0; mf < 2; ++mf)
#pragma unroll
        for (int nf = 0; nf < 8; ++nf) {
            const int gm = mBase + mf * 16;
            const int gn = nBase + nf * 8;
            *(float2*)&C[(size_t)gm * Nout + gn] =
                make_float2(acc[mf][nf][0], acc[mf][nf][1]);
            *(float2*)&C[(size_t)(gm + 8) * Nout + gn] =
                make_float2(acc[mf][nf][2], acc[mf][nf][3]);
        }
}

// ----------------------------------------------------------------------------
// Flash attention, fp32 (unchanged from round 0).
// ----------------------------------------------------------------------------
#define FA_BR  64
#define FA_BC  64
#define FA_HD  64
#define FA_LDP 68

#define FA_SMEM_FLOATS (3 * FA_HD * FA_LDP + FA_BC * FA_HD)
#define FA_SMEM_BYTES  (FA_SMEM_FLOATS * 4)

__global__ __launch_bounds__(256, 2)
void flash_attn(const float* __restrict__ Qp, const float* __restrict__ Kp,
                const float* __restrict__ Vp, float* __restrict__ Out,
                int S, int H)
{
    extern __shared__ float sm[];
    float* Qt = sm;
    float* Kt = Qt + FA_HD * FA_LDP;
    float* Pt = Kt + FA_HD * FA_LDP;
    float* Vs = Pt + FA_BC * FA_LDP;

    const int tid = threadIdx.x;
    const int ty = tid >> 4;
    const int tx = tid & 15;
    const int D = H * FA_HD;

    const int qblk = blockIdx.x;
    const int bh = blockIdx.y;
    const int b = bh / H;
    const int h = bh % H;

    const float* Qbase = Qp + (size_t)(b * S + qblk * FA_BR) * D + h * FA_HD;
    const float* Kbase = Kp + (size_t)(b * S) * D + h * FA_HD;
    const float* Vbase = Vp + (size_t)(b * S) * D + h * FA_HD;

    const float qscale = 0.125f * 1.4426950408889634f;

    {
        const int row = tid >> 2;
        const int c0 = (tid & 3) << 4;
#pragma unroll
        for (int u = 0; u < 4; ++u) {
            float4 v = *(const float4*)(Qbase + (size_t)row * D + c0 + 4 * u);
            Qt[(c0 + 4 * u + 0) * FA_LDP + row] = v.x * qscale;
            Qt[(c0 + 4 * u + 1) * FA_LDP + row] = v.y * qscale;
            Qt[(c0 + 4 * u + 2) * FA_LDP + row] = v.z * qscale;
            Qt[(c0 + 4 * u + 3) * FA_LDP + row] = v.w * qscale;
        }
    }

    float m_i[4], l_i[4], o[4][4];
#pragma unroll
    for (int r = 0; r < 4; ++r) {
        m_i[r] = -1e30f;
        l_i[r] = 0.f;
#pragma unroll
        for (int c = 0; c < 4; ++c) o[r][c] = 0.f;
    }

    const int nkv = S / FA_BC;
    for (int kv = 0; kv < nkv; ++kv) {
        __syncthreads();
        {
            const int row = tid >> 2;
            const int c0 = (tid & 3) << 4;
            const float* kp = Kbase + (size_t)(kv * FA_BC + row) * D + c0;
            const float* vp = Vbase + (size_t)(kv * FA_BC + row) * D + c0;
#pragma unroll
            for (int u = 0; u < 4; ++u) {
                float4 kk = *(const float4*)(kp + 4 * u);
                Kt[(c0 + 4 * u + 0) * FA_LDP + row] = kk.x;
                Kt[(c0 + 4 * u + 1) * FA_LDP + row] = kk.y;
                Kt[(c0 + 4 * u + 2) * FA_LDP + row] = kk.z;
                Kt[(c0 + 4 * u + 3) * FA_LDP + row] = kk.w;
                *(float4*)&Vs[row * FA_HD + c0 + 4 * u] = *(const float4*)(vp + 4 * u);
            }
        }
        __syncthreads();

        float s[4][4];
#pragma unroll
        for (int r = 0; r < 4; ++r)
#pragma unroll
            for (int c = 0; c < 4; ++c) s[r][c] = 0.f;

#pragma unroll 8
        for (int d = 0; d < FA_HD; ++d) {
            float4 qv = *(const float4*)&Qt[d * FA_LDP + ty * 4];
            float4 kvv = *(const float4*)&Kt[d * FA_LDP + tx * 4];
            float qa[4] = {qv.x, qv.y, qv.z, qv.w};
            float ka[4] = {kvv.x, kvv.y, kvv.z, kvv.w};
#pragma unroll
            for (int r = 0; r < 4; ++r)
#pragma unroll
                for (int c = 0; c < 4; ++c)
                    s[r][c] = fmaf(qa[r], ka[c], s[r][c]);
        }

#pragma unroll
        for (int r = 0; r < 4; ++r) {
            float rm = fmaxf(fmaxf(s[r][0], s[r][1]), fmaxf(s[r][2], s[r][3]));
#pragma unroll
            for (int msk = 8; msk; msk >>= 1)
                rm = fmaxf(rm, __shfl_xor_sync(0xffffffffu, rm, msk));
            const float mnew = fmaxf(m_i[r], rm);
            const float alpha = exp2f(m_i[r] - mnew);
            float rs = 0.f;
#pragma unroll
            for (int c = 0; c < 4; ++c) {
                float p = exp2f(s[r][c] - mnew);
                s[r][c] = p;
                rs += p;
            }
#pragma unroll
            for (int msk = 8; msk; msk >>= 1)
                rs += __shfl_xor_sync(0xffffffffu, rs, msk);
            l_i[r] = l_i[r] * alpha + rs;
            m_i[r] = mnew;
#pragma unroll
            for (int c = 0; c < 4; ++c) o[r][c] *= alpha;
        }

#pragma unroll
        for (int r = 0; r < 4; ++r)
#pragma unroll
            for (int c = 0; c < 4; ++c)
                Pt[(tx * 4 + c) * FA_LDP + (ty * 4 + r)] = s[r][c];
        __syncthreads();

#pragma unroll 8
        for (int j = 0; j < FA_BC; ++j) {
            float4 pv = *(const float4*)&Pt[j * FA_LDP + ty * 4];
            float4 vv = *(const float4*)&Vs[j * FA_HD + tx * 4];
            float pa[4] = {pv.x, pv.y, pv.z, pv.w};
            float va[4] = {vv.x, vv.y, vv.z, vv.w};
#pragma unroll
            for (int r = 0; r < 4; ++r)
#pragma unroll
                for (int c = 0; c < 4; ++c)
                    o[r][c] = fmaf(pa[r], va[c], o[r][c]);
        }
    }

#pragma unroll
    for (int r = 0; r < 4; ++r) {
        const float inv = 1.f / l_i[r];
        float4 ov = make_float4(o[r][0] * inv, o[r][1] * inv,
                                o[r][2] * inv, o[r][3] * inv);
        *(float4*)&Out[(size_t)(b * S + qblk * FA_BR + ty * 4 + r) * D
                       + h * FA_HD + tx * 4] = ov;
    }
}

// ----------------------------------------------------------------------------
// Launch
// ----------------------------------------------------------------------------
extern "C" void kernel_launch(void* const* d_in, const int* in_sizes, int n_in,
                              void* d_out, int out_size)
{
    const float* x[3] = {(const float*)d_in[0], (const float*)d_in[1],
                         (const float*)d_in[2]};
    const float* w[3] = {(const float*)d_in[3], (const float*)d_in[4],
                         (const float*)d_in[5]};
    float* out = (float*)d_out;

    const int D = MHA_D, M = MHA_M, S = MHA_S, H = MHA_H;
    const int B = M / S;

    float *Qb, *Kb, *Vb;
    cudaGetSymbolAddress((void**)&Qb, g_Qp);
    cudaGetSymbolAddress((void**)&Kb, g_Kp);
    cudaGetSymbolAddress((void**)&Vb, g_Vp);
    __nv_bfloat16 *Ahi, *Alo, *Bhi, *Blo;
    cudaGetSymbolAddress((void**)&Ahi, g_Ahi);
    cudaGetSymbolAddress((void**)&Alo, g_Alo);
    cudaGetSymbolAddress((void**)&Bhi, g_Bhi);
    cudaGetSymbolAddress((void**)&Blo, g_Blo);
    float* outs[3] = {Qb, Kb, Vb};

    cudaFuncSetAttribute(gemm_mma_bf16x2,
                         cudaFuncAttributeMaxDynamicSharedMemorySize, GEMM_SMEM);
    cudaFuncSetAttribute(flash_attn,
                         cudaFuncAttributeMaxDynamicSharedMemorySize, FA_SMEM_BYTES);

    const int nElem = M * D;
    for (int p = 0; p < 3; ++p) {
        convert_split<<<nElem / 4 / 256, 256>>>(x[p], Ahi, Alo, nElem);
        transpose_split<<<dim3(D / 32, D / 32), dim3(32, 8)>>>(w[p], Bhi, Blo, D);
        gemm_mma_bf16x2<<<dim3(D / G_BN, M / G_BM), 256, GEMM_SMEM>>>(
            Ahi, Alo, Bhi, Blo, outs[p], D, D);
    }

    dim3 fg(S / FA_BR, B * H);
    flash_attn<<<fg, 256, FA_SMEM_BYTES>>>(Qb, Kb, Vb, out, S, H);
}

// round 5
// speedup vs baseline: 2.3169x; 1.6907x over previous
#include <cuda_runtime.h>
#include <cuda_bf16.h>
#include <math.h>
#include <cstdint>

// ============================================================================
// MHA: out = softmax((XqWq)(XkWk)^T / sqrt(Hd)) (XvWv)
// B=8, S=1024, D=1024, H=16, Hd=64, fp32 in/out. Plain sm_100 (no tcgen05).
//
// Round 5: everything on mma.sync.m16n8k16 bf16 with hi/lo split precision.
//  - projections: 128x128x32 tiles, epilogue writes bf16 hi/lo directly
//  - attention:   flash_mma, warp-local softmax, P-frags from accumulators,
//                 V staged transposed so B-frags reuse the validated pattern
// ============================================================================

#define MHA_M   8192
#define MHA_D   1024
#define MHA_H   16
#define MHA_S   1024

__device__ __nv_bfloat16 g_Qhi[MHA_M * MHA_D];
__device__ __nv_bfloat16 g_Qlo[MHA_M * MHA_D];
__device__ __nv_bfloat16 g_Khi[MHA_M * MHA_D];
__device__ __nv_bfloat16 g_Klo[MHA_M * MHA_D];
__device__ __nv_bfloat16 g_Vhi[MHA_M * MHA_D];
__device__ __nv_bfloat16 g_Vlo[MHA_M * MHA_D];
__device__ __nv_bfloat16 g_Ahi[MHA_M * MHA_D];
__device__ __nv_bfloat16 g_Alo[MHA_M * MHA_D];
__device__ __nv_bfloat16 g_Bhi[MHA_D * MHA_D];   // W^T, [N][K]
__device__ __nv_bfloat16 g_Blo[MHA_D * MHA_D];

// ---------------------------------------------------------------------------
// helpers
// ---------------------------------------------------------------------------
__device__ __forceinline__ uint32_t smem_to_u32(const void* p) {
    uint32_t a;
    asm("{ .reg .u64 t; cvta.to.shared.u64 t, %1; cvt.u32.u64 %0, t; }"
        : "=r"(a) : "l"(p));
    return a;
}
__device__ __forceinline__ void ldm4(uint32_t* r, uint32_t addr) {
    asm volatile("ldmatrix.sync.aligned.m8n8.x4.shared.b16 {%0,%1,%2,%3}, [%4];"
                 : "=r"(r[0]), "=r"(r[1]), "=r"(r[2]), "=r"(r[3]) : "r"(addr));
}
__device__ __forceinline__ void mma_bf16(float* d, const uint32_t* a,
                                         const uint32_t* b) {
    asm volatile(
        "mma.sync.aligned.m16n8k16.row.col.f32.bf16.bf16.f32 "
        "{%0,%1,%2,%3}, {%4,%5,%6,%7}, {%8,%9}, {%0,%1,%2,%3};"
        : "+f"(d[0]), "+f"(d[1]), "+f"(d[2]), "+f"(d[3])
        : "r"(a[0]), "r"(a[1]), "r"(a[2]), "r"(a[3]), "r"(b[0]), "r"(b[1]));
}
__device__ __forceinline__ uint32_t packbf(float x, float y) {
    __nv_bfloat162 t = __floats2bfloat162_rn(x, y);
    return *reinterpret_cast<uint32_t*>(&t);
}
__device__ __forceinline__ float bfres(float x) {   // residual of bf16 rounding
    return x - __bfloat162float(__float2bfloat16_rn(x));
}

// ---------------------------------------------------------------------------
// fp32 -> bf16 hi/lo split (inputs)
// ---------------------------------------------------------------------------
__global__ void convert_split(const float* __restrict__ X,
                              __nv_bfloat16* __restrict__ hi,
                              __nv_bfloat16* __restrict__ lo, int n)
{
    int i = (blockIdx.x * blockDim.x + threadIdx.x) * 4;
    if (i >= n) return;
    float4 v = *(const float4*)(X + i);
    __nv_bfloat16 h0 = __float2bfloat16(v.x);
    __nv_bfloat16 h1 = __float2bfloat16(v.y);
    __nv_bfloat16 h2 = __float2bfloat16(v.z);
    __nv_bfloat16 h3 = __float2bfloat16(v.w);
    __nv_bfloat16 l0 = __float2bfloat16(v.x - __bfloat162float(h0));
    __nv_bfloat16 l1 = __float2bfloat16(v.y - __bfloat162float(h1));
    __nv_bfloat16 l2 = __float2bfloat16(v.z - __bfloat162float(h2));
    __nv_bfloat16 l3 = __float2bfloat16(v.w - __bfloat162float(h3));
    *(__nv_bfloat162*)(hi + i)     = __nv_bfloat162(h0, h1);
    *(__nv_bfloat162*)(hi + i + 2) = __nv_bfloat162(h2, h3);
    *(__nv_bfloat162*)(lo + i)     = __nv_bfloat162(l0, l1);
    *(__nv_bfloat162*)(lo + i + 2) = __nv_bfloat162(l2, l3);
}

// W [K,N] fp32 -> W^T [N,K] bf16 hi/lo
__global__ void transpose_split(const float* __restrict__ W,
                                __nv_bfloat16* __restrict__ hi,
                                __nv_bfloat16* __restrict__ lo, int Dm)
{
    __shared__ float t[32][33];
    const int bx = blockIdx.x * 32;
    const int by = blockIdx.y * 32;
    const int x = threadIdx.x, y = threadIdx.y;
#pragma unroll
    for (int j = 0; j < 4; ++j)
        t[y + 8 * j][x] = W[(size_t)(by + y + 8 * j) * Dm + bx + x];
    __syncthreads();
#pragma unroll
    for (int j = 0; j < 4; ++j) {
        float v = t[x][y + 8 * j];
        __nv_bfloat16 h = __float2bfloat16(v);
        __nv_bfloat16 l = __float2bfloat16(v - __bfloat162float(h));
        size_t o = (size_t)(bx + y + 8 * j) * Dm + by + x;
        hi[o] = h;
        lo[o] = l;
    }
}

// ---------------------------------------------------------------------------
// Projection GEMM (mma.sync bf16x2-split), epilogue -> bf16 hi/lo outputs.
// ---------------------------------------------------------------------------
#define G_BM 128
#define G_BN 128
#define G_BK 32
#define G_ROWB  48
#define G_SLAB  (128 * G_ROWB)
#define G_T_AHI 0
#define G_T_ALO (2 * G_SLAB)
#define G_T_BHI (4 * G_SLAB)
#define G_T_BLO (6 * G_SLAB)
#define G_STAGE (8 * G_SLAB)
#define GEMM_SMEM (2 * G_STAGE)         // 98304

__global__ __launch_bounds__(256, 1)
void gemm_mma_bf16x2(const __nv_bfloat16* __restrict__ Ahi,
                     const __nv_bfloat16* __restrict__ Alo,
                     const __nv_bfloat16* __restrict__ Bhi,
                     const __nv_bfloat16* __restrict__ Blo,
                     __nv_bfloat16* __restrict__ Chi,
                     __nv_bfloat16* __restrict__ Clo,
                     int K, int Nout)
{
    extern __shared__ char smem[];
    const uint32_t smem_base = smem_to_u32(smem);
    const int tid = threadIdx.x;
    const int lane = tid & 31;
    const int wid = tid >> 5;
    const int warp_row = wid >> 1;
    const int warp_col = wid & 1;
    const int m0 = blockIdx.y * G_BM;
    const int n0 = blockIdx.x * G_BN;

    int rowA[2], cA[2];
    uint32_t sOffT[2];
#pragma unroll
    for (int i = 0; i < 2; ++i) {
        int chunk = i * 256 + tid;
        rowA[i] = chunk >> 2;
        cA[i] = chunk & 3;
        sOffT[i] = (uint32_t)((cA[i] >> 1) * G_SLAB + rowA[i] * G_ROWB +
                              (cA[i] & 1) * 16);
    }

    const uint32_t aLM = (uint32_t)((warp_row * 32 + (lane & 15)) * G_ROWB +
                                    (lane >> 4) * 16);
    const uint32_t bLM = (uint32_t)((warp_col * 64 + ((lane >> 4) << 3) +
                                     (lane & 7)) * G_ROWB +
                                    ((lane >> 3) & 1) * 16);

    float acc[2][8][4];
#pragma unroll
    for (int mf = 0; mf < 2; ++mf)
#pragma unroll
        for (int nf = 0; nf < 8; ++nf)
#pragma unroll
            for (int q = 0; q < 4; ++q) acc[mf][nf][q] = 0.f;

#pragma unroll
    for (int i = 0; i < 2; ++i) {
        const size_t ga = (size_t)(m0 + rowA[i]) * K + cA[i] * 8;
        const size_t gb = (size_t)(n0 + rowA[i]) * K + cA[i] * 8;
        *(uint4*)(smem + G_T_AHI + sOffT[i]) = *(const uint4*)(Ahi + ga);
        *(uint4*)(smem + G_T_ALO + sOffT[i]) = *(const uint4*)(Alo + ga);
        *(uint4*)(smem + G_T_BHI + sOffT[i]) = *(const uint4*)(Bhi + gb);
        *(uint4*)(smem + G_T_BLO + sOffT[i]) = *(const uint4*)(Blo + gb);
    }
    __syncthreads();

    const int T = K / G_BK;
    for (int t = 0; t < T; ++t) {
        const int cur = t & 1;

        uint4 pf[8];
        if (t + 1 < T) {
            const int k0 = (t + 1) * G_BK;
#pragma unroll
            for (int i = 0; i < 2; ++i) {
                const size_t ga = (size_t)(m0 + rowA[i]) * K + k0 + cA[i] * 8;
                const size_t gb = (size_t)(n0 + rowA[i]) * K + k0 + cA[i] * 8;
                pf[i * 4 + 0] = *(const uint4*)(Ahi + ga);
                pf[i * 4 + 1] = *(const uint4*)(Alo + ga);
                pf[i * 4 + 2] = *(const uint4*)(Bhi + gb);
                pf[i * 4 + 3] = *(const uint4*)(Blo + gb);
            }
        }

        const uint32_t sb = smem_base + cur * G_STAGE;
#pragma unroll
        for (int kf = 0; kf < 2; ++kf) {
            const uint32_t kfo = kf * G_SLAB;
            uint32_t ah[2][4], al[2][4], bh[8][2], bl[8][2];
#pragma unroll
            for (int mf = 0; mf < 2; ++mf) {
                ldm4(ah[mf], sb + G_T_AHI + kfo + aLM + mf * 16 * G_ROWB);
                ldm4(al[mf], sb + G_T_ALO + kfo + aLM + mf * 16 * G_ROWB);
            }
#pragma unroll
            for (int pr = 0; pr < 4; ++pr) {
                uint32_t r[4];
                ldm4(r, sb + G_T_BHI + kfo + bLM + pr * 16 * G_ROWB);
                bh[pr * 2][0] = r[0]; bh[pr * 2][1] = r[1];
                bh[pr * 2 + 1][0] = r[2]; bh[pr * 2 + 1][1] = r[3];
                ldm4(r, sb + G_T_BLO + kfo + bLM + pr * 16 * G_ROWB);
                bl[pr * 2][0] = r[0]; bl[pr * 2][1] = r[1];
                bl[pr * 2 + 1][0] = r[2]; bl[pr * 2 + 1][1] = r[3];
            }
#pragma unroll
            for (int mf = 0; mf < 2; ++mf)
#pragma unroll
                for (int nf = 0; nf < 8; ++nf) {
                    mma_bf16(acc[mf][nf], ah[mf], bh[nf]);
                    mma_bf16(acc[mf][nf], ah[mf], bl[nf]);
                    mma_bf16(acc[mf][nf], al[mf], bh[nf]);
                }
        }

        if (t + 1 < T) {
            char* sn = smem + (cur ^ 1) * G_STAGE;
#pragma unroll
            for (int i = 0; i < 2; ++i) {
                *(uint4*)(sn + G_T_AHI + sOffT[i]) = pf[i * 4 + 0];
                *(uint4*)(sn + G_T_ALO + sOffT[i]) = pf[i * 4 + 1];
                *(uint4*)(sn + G_T_BHI + sOffT[i]) = pf[i * 4 + 2];
                *(uint4*)(sn + G_T_BLO + sOffT[i]) = pf[i * 4 + 3];
            }
        }
        __syncthreads();
    }

    // epilogue: split fp32 acc -> bf16 hi/lo, write packed pairs
    const int mBase = m0 + warp_row * 32 + (lane >> 2);
    const int nBase = n0 + warp_col * 64 + (lane & 3) * 2;
#pragma unroll
    for (int mf = 0; mf < 2; ++mf)
#pragma unroll
        for (int nf = 0; nf < 8; ++nf) {
            const int gm = mBase + mf * 16;
            const int gn = nBase + nf * 8;
            const float* a = acc[mf][nf];
            *(uint32_t*)&Chi[(size_t)gm * Nout + gn] = packbf(a[0], a[1]);
            *(uint32_t*)&Clo[(size_t)gm * Nout + gn] = packbf(bfres(a[0]), bfres(a[1]));
            *(uint32_t*)&Chi[(size_t)(gm + 8) * Nout + gn] = packbf(a[2], a[3]);
            *(uint32_t*)&Clo[(size_t)(gm + 8) * Nout + gn] = packbf(bfres(a[2]), bfres(a[3]));
        }
}

// ---------------------------------------------------------------------------
// Flash attention with mma.sync, bf16 hi/lo split everywhere.
// CTA = 128 Q rows x one (b,h), 8 warps x 16 rows. KV tiles of 64.
// Smem rows padded to 72 bf16 (144B): ldmatrix phase-conflict-free.
// V staged TRANSPOSED [d][j] so B-frags use the validated non-trans pattern.
// ---------------------------------------------------------------------------
#define FM_ROWB 144
#define FM_SQHI 0
#define FM_SQLO (FM_SQHI + 128 * FM_ROWB)    // 18432
#define FM_SKHI (FM_SQLO + 128 * FM_ROWB)    // 36864
#define FM_SKLO (FM_SKHI + 64 * FM_ROWB)     // 46080
#define FM_SVHI (FM_SKLO + 64 * FM_ROWB)     // 55296
#define FM_SVLO (FM_SVHI + 64 * FM_ROWB)     // 64512
#define FM_SMEM (FM_SVLO + 64 * FM_ROWB)     // 73728

__global__ __launch_bounds__(256, 2)
void flash_mma(const __nv_bfloat16* __restrict__ Qhi,
               const __nv_bfloat16* __restrict__ Qlo,
               const __nv_bfloat16* __restrict__ Khi,
               const __nv_bfloat16* __restrict__ Klo,
               const __nv_bfloat16* __restrict__ Vhi,
               const __nv_bfloat16* __restrict__ Vlo,
               float* __restrict__ Out, int S, int H)
{
    extern __shared__ char sm[];
    const uint32_t sb = smem_to_u32(sm);
    const int tid = threadIdx.x;
    const int lane = tid & 31;
    const int w = tid >> 5;
    const int D = H * 64;

    const int qblk = blockIdx.x;
    const int bh = blockIdx.y;
    const int b = bh / H;
    const int h = bh % H;

    const size_t qrow0 = (size_t)(b * S + qblk * 128);
    const size_t krow0 = (size_t)(b * S);

    const __nv_bfloat16* Qh = Qhi + qrow0 * D + h * 64;
    const __nv_bfloat16* Ql = Qlo + qrow0 * D + h * 64;

    // ---- load Q tile (128 x 64) hi/lo into smem, once ----
#pragma unroll
    for (int i = 0; i < 4; ++i) {
        const int ch = i * 256 + tid;        // 0..1023
        const int row = ch >> 3;
        const int c = ch & 7;
        *(uint4*)(sm + FM_SQHI + row * FM_ROWB + c * 16) =
            *(const uint4*)(Qh + (size_t)row * D + c * 8);
        *(uint4*)(sm + FM_SQLO + row * FM_ROWB + c * 16) =
            *(const uint4*)(Ql + (size_t)row * D + c * 8);
    }

    // frag address components (validated patterns from the gemm kernel)
    const uint32_t aOff = (uint32_t)((w * 16 + (lane & 15)) * FM_ROWB +
                                     ((lane >> 4) << 4));
    const uint32_t bRow = ((lane >> 4) << 3) + (lane & 7);
    const uint32_t bSeg = ((lane >> 3) & 1) << 4;

    float o[8][4];
    float sacc[8][4];
#pragma unroll
    for (int nf = 0; nf < 8; ++nf)
#pragma unroll
        for (int q = 0; q < 4; ++q) o[nf][q] = 0.f;
    float m0v = -1e30f, m1v = -1e30f, l0v = 0.f, l1v = 0.f;

    const float qs = 0.125f * 1.4426950408889634f;   // 1/sqrt(64) * log2(e)
    const int nkv = S / 64;

    for (int kv = 0; kv < nkv; ++kv) {
        __syncthreads();   // protect K/V smem from previous iteration readers

        // ---- load K tile (64x64) hi/lo; V tile transposed [d][j] hi/lo ----
        {
            const __nv_bfloat16* Kh = Khi + (krow0 + kv * 64) * D + h * 64;
            const __nv_bfloat16* Kl = Klo + (krow0 + kv * 64) * D + h * 64;
            const __nv_bfloat16* Vh = Vhi + (krow0 + kv * 64) * D + h * 64;
            const __nv_bfloat16* Vl = Vlo + (krow0 + kv * 64) * D + h * 64;
#pragma unroll
            for (int i = 0; i < 2; ++i) {
                const int ch = i * 256 + tid;  // 0..511
                const int row = ch >> 3;       // j
                const int c = ch & 7;
                *(uint4*)(sm + FM_SKHI + row * FM_ROWB + c * 16) =
                    *(const uint4*)(Kh + (size_t)row * D + c * 8);
                *(uint4*)(sm + FM_SKLO + row * FM_ROWB + c * 16) =
                    *(const uint4*)(Kl + (size_t)row * D + c * 8);
                // V transpose: read 8 bf16 of row j, write column j of rows d
                uint4 vh = *(const uint4*)(Vh + (size_t)row * D + c * 8);
                uint4 vl = *(const uint4*)(Vl + (size_t)row * D + c * 8);
                const unsigned short* ph = (const unsigned short*)&vh;
                const unsigned short* pl = (const unsigned short*)&vl;
#pragma unroll
                for (int u = 0; u < 8; ++u) {
                    *(unsigned short*)(sm + FM_SVHI + (c * 8 + u) * FM_ROWB + row * 2) = ph[u];
                    *(unsigned short*)(sm + FM_SVLO + (c * 8 + u) * FM_ROWB + row * 2) = pl[u];
                }
            }
        }
        __syncthreads();

        // ---- S = Q K^T (3-way split), 64 cols ----
#pragma unroll
        for (int nf = 0; nf < 8; ++nf)
#pragma unroll
            for (int q = 0; q < 4; ++q) sacc[nf][q] = 0.f;

#pragma unroll
        for (int kf = 0; kf < 4; ++kf) {
            uint32_t ah[4], al[4];
            ldm4(ah, sb + FM_SQHI + aOff + kf * 32);
            ldm4(al, sb + FM_SQLO + aOff + kf * 32);
            uint32_t bh_[8][2], bl_[8][2];
#pragma unroll
            for (int pr = 0; pr < 4; ++pr) {
                uint32_t r[4];
                ldm4(r, sb + FM_SKHI + (pr * 16 + bRow) * FM_ROWB + kf * 32 + bSeg);
                bh_[pr * 2][0] = r[0]; bh_[pr * 2][1] = r[1];
                bh_[pr * 2 + 1][0] = r[2]; bh_[pr * 2 + 1][1] = r[3];
                ldm4(r, sb + FM_SKLO + (pr * 16 + bRow) * FM_ROWB + kf * 32 + bSeg);
                bl_[pr * 2][0] = r[0]; bl_[pr * 2][1] = r[1];
                bl_[pr * 2 + 1][0] = r[2]; bl_[pr * 2 + 1][1] = r[3];
            }
#pragma unroll
            for (int nf = 0; nf < 8; ++nf) {
                mma_bf16(sacc[nf], ah, bh_[nf]);
                mma_bf16(sacc[nf], ah, bl_[nf]);
                mma_bf16(sacc[nf], al, bh_[nf]);
            }
        }

        // ---- online softmax (warp-local rows; quad shuffle reductions) ----
        float rm0 = -1e30f, rm1 = -1e30f;
#pragma unroll
        for (int nf = 0; nf < 8; ++nf) {
#pragma unroll
            for (int q = 0; q < 4; ++q) sacc[nf][q] *= qs;
            rm0 = fmaxf(rm0, fmaxf(sacc[nf][0], sacc[nf][1]));
            rm1 = fmaxf(rm1, fmaxf(sacc[nf][2], sacc[nf][3]));
        }
        rm0 = fmaxf(rm0, __shfl_xor_sync(0xffffffffu, rm0, 1));
        rm0 = fmaxf(rm0, __shfl_xor_sync(0xffffffffu, rm0, 2));
        rm1 = fmaxf(rm1, __shfl_xor_sync(0xffffffffu, rm1, 1));
        rm1 = fmaxf(rm1, __shfl_xor_sync(0xffffffffu, rm1, 2));

        const float mn0 = fmaxf(m0v, rm0);
        const float mn1 = fmaxf(m1v, rm1);
        const float a0 = exp2f(m0v - mn0);
        const float a1 = exp2f(m1v - mn1);
        float rs0 = 0.f, rs1 = 0.f;
#pragma unroll
        for (int nf = 0; nf < 8; ++nf) {
            float p0 = exp2f(sacc[nf][0] - mn0);
            float p1 = exp2f(sacc[nf][1] - mn0);
            float p2 = exp2f(sacc[nf][2] - mn1);
            float p3 = exp2f(sacc[nf][3] - mn1);
            sacc[nf][0] = p0; sacc[nf][1] = p1;
            sacc[nf][2] = p2; sacc[nf][3] = p3;
            rs0 += p0 + p1;
            rs1 += p2 + p3;
        }
        rs0 += __shfl_xor_sync(0xffffffffu, rs0, 1);
        rs0 += __shfl_xor_sync(0xffffffffu, rs0, 2);
        rs1 += __shfl_xor_sync(0xffffffffu, rs1, 1);
        rs1 += __shfl_xor_sync(0xffffffffu, rs1, 2);
        l0v = l0v * a0 + rs0;
        l1v = l1v * a1 + rs1;
        m0v = mn0; m1v = mn1;
#pragma unroll
        for (int nf = 0; nf < 8; ++nf) {
            o[nf][0] *= a0; o[nf][1] *= a0;
            o[nf][2] *= a1; o[nf][3] *= a1;
        }

        // ---- O += P V : P A-frags from accumulators, V B-frags from smem ----
#pragma unroll
        for (int jf = 0; jf < 4; ++jf) {
            const float* p0 = sacc[2 * jf];
            const float* p1 = sacc[2 * jf + 1];
            uint32_t aph[4], apl[4];
            aph[0] = packbf(p0[0], p0[1]);
            aph[1] = packbf(p0[2], p0[3]);
            aph[2] = packbf(p1[0], p1[1]);
            aph[3] = packbf(p1[2], p1[3]);
            apl[0] = packbf(bfres(p0[0]), bfres(p0[1]));
            apl[1] = packbf(bfres(p0[2]), bfres(p0[3]));
            apl[2] = packbf(bfres(p1[0]), bfres(p1[1]));
            apl[3] = packbf(bfres(p1[2]), bfres(p1[3]));
#pragma unroll
            for (int pr = 0; pr < 4; ++pr) {
                uint32_t rv[4], rl[4];
                ldm4(rv, sb + FM_SVHI + (pr * 16 + bRow) * FM_ROWB + jf * 32 + bSeg);
                ldm4(rl, sb + FM_SVLO + (pr * 16 + bRow) * FM_ROWB + jf * 32 + bSeg);
                uint32_t bvh0[2] = {rv[0], rv[1]}, bvh1[2] = {rv[2], rv[3]};
                uint32_t bvl0[2] = {rl[0], rl[1]}, bvl1[2] = {rl[2], rl[3]};
                mma_bf16(o[pr * 2], aph, bvh0);
                mma_bf16(o[pr * 2], aph, bvl0);
                mma_bf16(o[pr * 2], apl, bvh0);
                mma_bf16(o[pr * 2 + 1], aph, bvh1);
                mma_bf16(o[pr * 2 + 1], aph, bvl1);
                mma_bf16(o[pr * 2 + 1], apl, bvh1);
            }
        }
    }

    // ---- epilogue ----
    const float inv0 = 1.f / l0v;
    const float inv1 = 1.f / l1v;
    const int r0 = lane >> 2;
    const int c2 = (lane & 3) * 2;
    float* O0 = Out + (qrow0 + w * 16 + r0) * D + h * 64;
#pragma unroll
    for (int nf = 0; nf < 8; ++nf) {
        *(float2*)(O0 + nf * 8 + c2) =
            make_float2(o[nf][0] * inv0, o[nf][1] * inv0);
        *(float2*)(O0 + (size_t)8 * D + nf * 8 + c2) =
            make_float2(o[nf][2] * inv1, o[nf][3] * inv1);
    }
}

// ----------------------------------------------------------------------------
// Launch
// ----------------------------------------------------------------------------
extern "C" void kernel_launch(void* const* d_in, const int* in_sizes, int n_in,
                              void* d_out, int out_size)
{
    const float* x[3] = {(const float*)d_in[0], (const float*)d_in[1],
                         (const float*)d_in[2]};
    const float* w[3] = {(const float*)d_in[3], (const float*)d_in[4],
                         (const float*)d_in[5]};
    float* out = (float*)d_out;

    const int D = MHA_D, M = MHA_M, S = MHA_S, H = MHA_H;
    const int B = M / S;

    __nv_bfloat16 *Qhi, *Qlo, *Khi, *Klo, *Vhi, *Vlo, *Ahi, *Alo, *Bhi, *Blo;
    cudaGetSymbolAddress((void**)&Qhi, g_Qhi);
    cudaGetSymbolAddress((void**)&Qlo, g_Qlo);
    cudaGetSymbolAddress((void**)&Khi, g_Khi);
    cudaGetSymbolAddress((void**)&Klo, g_Klo);
    cudaGetSymbolAddress((void**)&Vhi, g_Vhi);
    cudaGetSymbolAddress((void**)&Vlo, g_Vlo);
    cudaGetSymbolAddress((void**)&Ahi, g_Ahi);
    cudaGetSymbolAddress((void**)&Alo, g_Alo);
    cudaGetSymbolAddress((void**)&Bhi, g_Bhi);
    cudaGetSymbolAddress((void**)&Blo, g_Blo);

    __nv_bfloat16* outs_hi[3] = {Qhi, Khi, Vhi};
    __nv_bfloat16* outs_lo[3] = {Qlo, Klo, Vlo};

    cudaFuncSetAttribute(gemm_mma_bf16x2,
                         cudaFuncAttributeMaxDynamicSharedMemorySize, GEMM_SMEM);
    cudaFuncSetAttribute(flash_mma,
                         cudaFuncAttributeMaxDynamicSharedMemorySize, FM_SMEM);

    const int nElem = M * D;
    for (int p = 0; p < 3; ++p) {
        convert_split<<<nElem / 4 / 256, 256>>>(x[p], Ahi, Alo, nElem);
        transpose_split<<<dim3(D / 32, D / 32), dim3(32, 8)>>>(w[p], Bhi, Blo, D);
        gemm_mma_bf16x2<<<dim3(D / G_BN, M / G_BM), 256, GEMM_SMEM>>>(
            Ahi, Alo, Bhi, Blo, outs_hi[p], outs_lo[p], D, D);
    }

    dim3 fg(S / 128, B * H);   // (8, 128)
    flash_mma<<<fg, 256, FM_SMEM>>>(Qhi, Qlo, Khi, Klo, Vhi, Vlo, out, S, H);
}

// round 8
// speedup vs baseline: 2.4915x; 1.0754x over previous
#include <cuda_runtime.h>
#include <cuda_bf16.h>
#include <math.h>
#include <cstdint>

// ============================================================================
// MHA: out = softmax((XqWq)(XkWk)^T / sqrt(Hd)) (XvWv)
// B=8, S=1024, D=1024, H=16, Hd=64, fp32 in/out. Plain sm_100 (no tcgen05).
//
// Round 8: same theory as R6 (warp tile 64x64, 4 warps, 2 CTAs/SM, fused
// fp32->bf16 hi/lo A-conversion) but de-risked implementation: no cp.async,
// no macro stage-fill — plain synchronous fill after compute, cross-CTA
// overlap via occupancy 2. Flash attention identical to the R5 passing kernel.
// ============================================================================

#define MHA_M   8192
#define MHA_D   1024
#define MHA_H   16
#define MHA_S   1024

__device__ __nv_bfloat16 g_Qhi[MHA_M * MHA_D];
__device__ __nv_bfloat16 g_Qlo[MHA_M * MHA_D];
__device__ __nv_bfloat16 g_Khi[MHA_M * MHA_D];
__device__ __nv_bfloat16 g_Klo[MHA_M * MHA_D];
__device__ __nv_bfloat16 g_Vhi[MHA_M * MHA_D];
__device__ __nv_bfloat16 g_Vlo[MHA_M * MHA_D];
__device__ __nv_bfloat16 g_Bhi[MHA_D * MHA_D];   // W^T, [N][K]
__device__ __nv_bfloat16 g_Blo[MHA_D * MHA_D];

// ---------------------------------------------------------------------------
// helpers
// ---------------------------------------------------------------------------
__device__ __forceinline__ uint32_t smem_to_u32(const void* p) {
    uint32_t a;
    asm("{ .reg .u64 t; cvta.to.shared.u64 t, %1; cvt.u32.u64 %0, t; }"
        : "=r"(a) : "l"(p));
    return a;
}
__device__ __forceinline__ void ldm4(uint32_t* r, uint32_t addr) {
    asm volatile("ldmatrix.sync.aligned.m8n8.x4.shared.b16 {%0,%1,%2,%3}, [%4];"
                 : "=r"(r[0]), "=r"(r[1]), "=r"(r[2]), "=r"(r[3]) : "r"(addr));
}
__device__ __forceinline__ void mma_bf16(float* d, const uint32_t* a,
                                         const uint32_t* b) {
    asm volatile(
        "mma.sync.aligned.m16n8k16.row.col.f32.bf16.bf16.f32 "
        "{%0,%1,%2,%3}, {%4,%5,%6,%7}, {%8,%9}, {%0,%1,%2,%3};"
        : "+f"(d[0]), "+f"(d[1]), "+f"(d[2]), "+f"(d[3])
        : "r"(a[0]), "r"(a[1]), "r"(a[2]), "r"(a[3]), "r"(b[0]), "r"(b[1]));
}
__device__ __forceinline__ uint32_t packbf(float x, float y) {
    __nv_bfloat162 t = __floats2bfloat162_rn(x, y);
    return *reinterpret_cast<uint32_t*>(&t);
}
__device__ __forceinline__ float bfres(float x) {
    return x - __bfloat162float(__float2bfloat16_rn(x));
}

// ---------------------------------------------------------------------------
// W [K,N] fp32 -> W^T [N,K] bf16 hi/lo
// ---------------------------------------------------------------------------
__global__ void transpose_split(const float* __restrict__ W,
                                __nv_bfloat16* __restrict__ hi,
                                __nv_bfloat16* __restrict__ lo, int Dm)
{
    __shared__ float t[32][33];
    const int bx = blockIdx.x * 32;
    const int by = blockIdx.y * 32;
    const int x = threadIdx.x, y = threadIdx.y;
#pragma unroll
    for (int j = 0; j < 4; ++j)
        t[y + 8 * j][x] = W[(size_t)(by + y + 8 * j) * Dm + bx + x];
    __syncthreads();
#pragma unroll
    for (int j = 0; j < 4; ++j) {
        float v = t[x][y + 8 * j];
        __nv_bfloat16 h = __float2bfloat16(v);
        __nv_bfloat16 l = __float2bfloat16(v - __bfloat162float(h));
        size_t o = (size_t)(bx + y + 8 * j) * Dm + by + x;
        hi[o] = h;
        lo[o] = l;
    }
}

// ---------------------------------------------------------------------------
// Projection GEMM: A = fp32 X (converted to hi/lo in-kernel), B = bf16 hi/lo.
// CTA 128x128, BK=32, 128 threads = 4 warps (2x2 grid of 64x64 warp tiles).
// Double-buffered smem; stage fill is synchronous, after compute; latency
// hidden by the second CTA on the SM. Epilogue writes bf16 hi/lo.
// ---------------------------------------------------------------------------
#define G_ROWB  48
#define G_SLAB  (128 * G_ROWB)          // 6144
#define G_T_AHI 0
#define G_T_ALO (2 * G_SLAB)
#define G_T_BHI (4 * G_SLAB)
#define G_T_BLO (6 * G_SLAB)
#define G_STAGE (8 * G_SLAB)            // 49152
#define GEMM_SMEM (2 * G_STAGE)         // 98304

__global__ __launch_bounds__(128, 2)
void gemm_fused(const float* __restrict__ X,
                const __nv_bfloat16* __restrict__ Bhi,
                const __nv_bfloat16* __restrict__ Blo,
                __nv_bfloat16* __restrict__ Chi,
                __nv_bfloat16* __restrict__ Clo,
                int K, int Nout)
{
    extern __shared__ char smem[];
    const int tid = threadIdx.x;
    const int lane = tid & 31;
    const int wid = tid >> 5;
    const int warp_row = wid >> 1;      // 0..1
    const int warp_col = wid & 1;       // 0..1
    const int m0 = blockIdx.y * 128;
    const int n0 = blockIdx.x * 128;
    const uint32_t smem_base = smem_to_u32(smem);

    // chunk mapping: 4 chunks/thread; chunk = 8 elements of one row
    int rowC[4], c8[4];
    uint32_t sOffT[4];
#pragma unroll
    for (int i = 0; i < 4; ++i) {
        int ch = i * 128 + tid;
        rowC[i] = ch >> 2;
        c8[i] = ch & 3;
        sOffT[i] = (uint32_t)((c8[i] >> 1) * G_SLAB + rowC[i] * G_ROWB +
                              (c8[i] & 1) * 16);
    }

    // ldmatrix patterns (hardware-validated in rounds 4-5)
    const uint32_t aLM = (uint32_t)((warp_row * 64 + (lane & 15)) * G_ROWB +
                                    (lane >> 4) * 16);
    const uint32_t bLM = (uint32_t)((warp_col * 64 + ((lane >> 4) << 3) +
                                     (lane & 7)) * G_ROWB +
                                    ((lane >> 3) & 1) * 16);

    // stage fill: load fp32 A (convert to hi/lo) and bf16 B hi/lo
    auto fill_stage = [&](int stage, int k0) {
        char* base = smem + stage * G_STAGE;
#pragma unroll
        for (int i = 0; i < 4; ++i) {
            const float* gp = X + (size_t)(m0 + rowC[i]) * K + k0 + c8[i] * 8;
            float4 v0 = *(const float4*)gp;
            float4 v1 = *(const float4*)(gp + 4);
            uint32_t hbuf[4], lbuf[4];
            hbuf[0] = packbf(v0.x, v0.y);
            hbuf[1] = packbf(v0.z, v0.w);
            hbuf[2] = packbf(v1.x, v1.y);
            hbuf[3] = packbf(v1.z, v1.w);
            lbuf[0] = packbf(bfres(v0.x), bfres(v0.y));
            lbuf[1] = packbf(bfres(v0.z), bfres(v0.w));
            lbuf[2] = packbf(bfres(v1.x), bfres(v1.y));
            lbuf[3] = packbf(bfres(v1.z), bfres(v1.w));
            const size_t gb = (size_t)(n0 + rowC[i]) * K + k0 + c8[i] * 8;
            uint4 bh = *(const uint4*)(Bhi + gb);
            uint4 bl = *(const uint4*)(Blo + gb);
            *(uint4*)(base + G_T_AHI + sOffT[i]) = *(uint4*)hbuf;
            *(uint4*)(base + G_T_ALO + sOffT[i]) = *(uint4*)lbuf;
            *(uint4*)(base + G_T_BHI + sOffT[i]) = bh;
            *(uint4*)(base + G_T_BLO + sOffT[i]) = bl;
        }
    };

    float acc[4][8][4];
#pragma unroll
    for (int mf = 0; mf < 4; ++mf)
#pragma unroll
        for (int nf = 0; nf < 8; ++nf)
#pragma unroll
            for (int q = 0; q < 4; ++q) acc[mf][nf][q] = 0.f;

    fill_stage(0, 0);
    __syncthreads();

    const int T = K / 32;
    for (int t = 0; t < T; ++t) {
        const int cur = t & 1;
        const uint32_t sb = smem_base + cur * G_STAGE;
#pragma unroll
        for (int kf = 0; kf < 2; ++kf) {
            const uint32_t kfo = kf * G_SLAB;
            uint32_t ah[4][4], al[4][4];
#pragma unroll
            for (int mf = 0; mf < 4; ++mf) {
                ldm4(ah[mf], sb + G_T_AHI + kfo + aLM + mf * 16 * G_ROWB);
                ldm4(al[mf], sb + G_T_ALO + kfo + aLM + mf * 16 * G_ROWB);
            }
#pragma unroll
            for (int pr = 0; pr < 4; ++pr) {
                uint32_t rh[4], rl[4];
                ldm4(rh, sb + G_T_BHI + kfo + bLM + pr * 16 * G_ROWB);
                ldm4(rl, sb + G_T_BLO + kfo + bLM + pr * 16 * G_ROWB);
                uint32_t bh0[2] = {rh[0], rh[1]}, bh1[2] = {rh[2], rh[3]};
                uint32_t bl0[2] = {rl[0], rl[1]}, bl1[2] = {rl[2], rl[3]};
#pragma unroll
                for (int mf = 0; mf < 4; ++mf) {
                    mma_bf16(acc[mf][pr * 2], ah[mf], bh0);
                    mma_bf16(acc[mf][pr * 2], ah[mf], bl0);
                    mma_bf16(acc[mf][pr * 2], al[mf], bh0);
                    mma_bf16(acc[mf][pr * 2 + 1], ah[mf], bh1);
                    mma_bf16(acc[mf][pr * 2 + 1], ah[mf], bl1);
                    mma_bf16(acc[mf][pr * 2 + 1], al[mf], bh1);
                }
            }
        }

        if (t + 1 < T) fill_stage(cur ^ 1, (t + 1) * 32);
        __syncthreads();
    }

    // epilogue: split fp32 acc -> bf16 hi/lo
    const int mBase = m0 + warp_row * 64 + (lane >> 2);
    const int nBase = n0 + warp_col * 64 + (lane & 3) * 2;
#pragma unroll
    for (int mf = 0; mf < 4; ++mf)
#pragma unroll
        for (int nf = 0; nf < 8; ++nf) {
            const int gm = mBase + mf * 16;
            const int gn = nBase + nf * 8;
            const float* a = acc[mf][nf];
            *(uint32_t*)&Chi[(size_t)gm * Nout + gn] = packbf(a[0], a[1]);
            *(uint32_t*)&Clo[(size_t)gm * Nout + gn] = packbf(bfres(a[0]), bfres(a[1]));
            *(uint32_t*)&Chi[(size_t)(gm + 8) * Nout + gn] = packbf(a[2], a[3]);
            *(uint32_t*)&Clo[(size_t)(gm + 8) * Nout + gn] = packbf(bfres(a[2]), bfres(a[3]));
        }
}

// ---------------------------------------------------------------------------
// Flash attention with mma.sync (identical to the round-5 passing kernel).
// ---------------------------------------------------------------------------
#define FM_ROWB 144
#define FM_SQHI 0
#define FM_SQLO (FM_SQHI + 128 * FM_ROWB)
#define FM_SKHI (FM_SQLO + 128 * FM_ROWB)
#define FM_SKLO (FM_SKHI + 64 * FM_ROWB)
#define FM_SVHI (FM_SKLO + 64 * FM_ROWB)
#define FM_SVLO (FM_SVHI + 64 * FM_ROWB)
#define FM_SMEM (FM_SVLO + 64 * FM_ROWB)     // 73728

__global__ __launch_bounds__(256, 2)
void flash_mma(const __nv_bfloat16* __restrict__ Qhi,
               const __nv_bfloat16* __restrict__ Qlo,
               const __nv_bfloat16* __restrict__ Khi,
               const __nv_bfloat16* __restrict__ Klo,
               const __nv_bfloat16* __restrict__ Vhi,
               const __nv_bfloat16* __restrict__ Vlo,
               float* __restrict__ Out, int S, int H)
{
    extern __shared__ char sm[];
    const uint32_t sb = smem_to_u32(sm);
    const int tid = threadIdx.x;
    const int lane = tid & 31;
    const int w = tid >> 5;
    const int D = H * 64;

    const int qblk = blockIdx.x;
    const int bh = blockIdx.y;
    const int b = bh / H;
    const int h = bh % H;

    const size_t qrow0 = (size_t)(b * S + qblk * 128);
    const size_t krow0 = (size_t)(b * S);

    const __nv_bfloat16* Qh = Qhi + qrow0 * D + h * 64;
    const __nv_bfloat16* Ql = Qlo + qrow0 * D + h * 64;

#pragma unroll
    for (int i = 0; i < 4; ++i) {
        const int ch = i * 256 + tid;
        const int row = ch >> 3;
        const int c = ch & 7;
        *(uint4*)(sm + FM_SQHI + row * FM_ROWB + c * 16) =
            *(const uint4*)(Qh + (size_t)row * D + c * 8);
        *(uint4*)(sm + FM_SQLO + row * FM_ROWB + c * 16) =
            *(const uint4*)(Ql + (size_t)row * D + c * 8);
    }

    const uint32_t aOff = (uint32_t)((w * 16 + (lane & 15)) * FM_ROWB +
                                     ((lane >> 4) << 4));
    const uint32_t bRow = ((lane >> 4) << 3) + (lane & 7);
    const uint32_t bSeg = ((lane >> 3) & 1) << 4;

    float o[8][4];
    float sacc[8][4];
#pragma unroll
    for (int nf = 0; nf < 8; ++nf)
#pragma unroll
        for (int q = 0; q < 4; ++q) o[nf][q] = 0.f;
    float m0v = -1e30f, m1v = -1e30f, l0v = 0.f, l1v = 0.f;

    const float qs = 0.125f * 1.4426950408889634f;
    const int nkv = S / 64;

    for (int kv = 0; kv < nkv; ++kv) {
        __syncthreads();
        {
            const __nv_bfloat16* Kh = Khi + (krow0 + kv * 64) * D + h * 64;
            const __nv_bfloat16* Kl = Klo + (krow0 + kv * 64) * D + h * 64;
            const __nv_bfloat16* Vh = Vhi + (krow0 + kv * 64) * D + h * 64;
            const __nv_bfloat16* Vl = Vlo + (krow0 + kv * 64) * D + h * 64;
#pragma unroll
            for (int i = 0; i < 2; ++i) {
                const int ch = i * 256 + tid;
                const int row = ch >> 3;
                const int c = ch & 7;
                *(uint4*)(sm + FM_SKHI + row * FM_ROWB + c * 16) =
                    *(const uint4*)(Kh + (size_t)row * D + c * 8);
                *(uint4*)(sm + FM_SKLO + row * FM_ROWB + c * 16) =
                    *(const uint4*)(Kl + (size_t)row * D + c * 8);
                uint4 vh = *(const uint4*)(Vh + (size_t)row * D + c * 8);
                uint4 vl = *(const uint4*)(Vl + (size_t)row * D + c * 8);
                const unsigned short* ph = (const unsigned short*)&vh;
                const unsigned short* pl = (const unsigned short*)&vl;
#pragma unroll
                for (int u = 0; u < 8; ++u) {
                    *(unsigned short*)(sm + FM_SVHI + (c * 8 + u) * FM_ROWB + row * 2) = ph[u];
                    *(unsigned short*)(sm + FM_SVLO + (c * 8 + u) * FM_ROWB + row * 2) = pl[u];
                }
            }
        }
        __syncthreads();

#pragma unroll
        for (int nf = 0; nf < 8; ++nf)
#pragma unroll
            for (int q = 0; q < 4; ++q) sacc[nf][q] = 0.f;

#pragma unroll
        for (int kf = 0; kf < 4; ++kf) {
            uint32_t ah[4], al[4];
            ldm4(ah, sb + FM_SQHI + aOff + kf * 32);
            ldm4(al, sb + FM_SQLO + aOff + kf * 32);
            uint32_t bh_[8][2], bl_[8][2];
#pragma unroll
            for (int pr = 0; pr < 4; ++pr) {
                uint32_t r[4];
                ldm4(r, sb + FM_SKHI + (pr * 16 + bRow) * FM_ROWB + kf * 32 + bSeg);
                bh_[pr * 2][0] = r[0]; bh_[pr * 2][1] = r[1];
                bh_[pr * 2 + 1][0] = r[2]; bh_[pr * 2 + 1][1] = r[3];
                ldm4(r, sb + FM_SKLO + (pr * 16 + bRow) * FM_ROWB + kf * 32 + bSeg);
                bl_[pr * 2][0] = r[0]; bl_[pr * 2][1] = r[1];
                bl_[pr * 2 + 1][0] = r[2]; bl_[pr * 2 + 1][1] = r[3];
            }
#pragma unroll
            for (int nf = 0; nf < 8; ++nf) {
                mma_bf16(sacc[nf], ah, bh_[nf]);
                mma_bf16(sacc[nf], ah, bl_[nf]);
                mma_bf16(sacc[nf], al, bh_[nf]);
            }
        }

        float rm0 = -1e30f, rm1 = -1e30f;
#pragma unroll
        for (int nf = 0; nf < 8; ++nf) {
#pragma unroll
            for (int q = 0; q < 4; ++q) sacc[nf][q] *= qs;
            rm0 = fmaxf(rm0, fmaxf(sacc[nf][0], sacc[nf][1]));
            rm1 = fmaxf(rm1, fmaxf(sacc[nf][2], sacc[nf][3]));
        }
        rm0 = fmaxf(rm0, __shfl_xor_sync(0xffffffffu, rm0, 1));
        rm0 = fmaxf(rm0, __shfl_xor_sync(0xffffffffu, rm0, 2));
        rm1 = fmaxf(rm1, __shfl_xor_sync(0xffffffffu, rm1, 1));
        rm1 = fmaxf(rm1, __shfl_xor_sync(0xffffffffu, rm1, 2));

        const float mn0 = fmaxf(m0v, rm0);
        const float mn1 = fmaxf(m1v, rm1);
        const float a0 = exp2f(m0v - mn0);
        const float a1 = exp2f(m1v - mn1);
        float rs0 = 0.f, rs1 = 0.f;
#pragma unroll
        for (int nf = 0; nf < 8; ++nf) {
            float p0 = exp2f(sacc[nf][0] - mn0);
            float p1 = exp2f(sacc[nf][1] - mn0);
            float p2 = exp2f(sacc[nf][2] - mn1);
            float p3 = exp2f(sacc[nf][3] - mn1);
            sacc[nf][0] = p0; sacc[nf][1] = p1;
            sacc[nf][2] = p2; sacc[nf][3] = p3;
            rs0 += p0 + p1;
            rs1 += p2 + p3;
        }
        rs0 += __shfl_xor_sync(0xffffffffu, rs0, 1);
        rs0 += __shfl_xor_sync(0xffffffffu, rs0, 2);
        rs1 += __shfl_xor_sync(0xffffffffu, rs1, 1);
        rs1 += __shfl_xor_sync(0xffffffffu, rs1, 2);
        l0v = l0v * a0 + rs0;
        l1v = l1v * a1 + rs1;
        m0v = mn0; m1v = mn1;
#pragma unroll
        for (int nf = 0; nf < 8; ++nf) {
            o[nf][0] *= a0; o[nf][1] *= a0;
            o[nf][2] *= a1; o[nf][3] *= a1;
        }

#pragma unroll
        for (int jf = 0; jf < 4; ++jf) {
            const float* p0 = sacc[2 * jf];
            const float* p1 = sacc[2 * jf + 1];
            uint32_t aph[4], apl[4];
            aph[0] = packbf(p0[0], p0[1]);
            aph[1] = packbf(p0[2], p0[3]);
            aph[2] = packbf(p1[0], p1[1]);
            aph[3] = packbf(p1[2], p1[3]);
            apl[0] = packbf(bfres(p0[0]), bfres(p0[1]));
            apl[1] = packbf(bfres(p0[2]), bfres(p0[3]));
            apl[2] = packbf(bfres(p1[0]), bfres(p1[1]));
            apl[3] = packbf(bfres(p1[2]), bfres(p1[3]));
#pragma unroll
            for (int pr = 0; pr < 4; ++pr) {
                uint32_t rv[4], rl[4];
                ldm4(rv, sb + FM_SVHI + (pr * 16 + bRow) * FM_ROWB + jf * 32 + bSeg);
                ldm4(rl, sb + FM_SVLO + (pr * 16 + bRow) * FM_ROWB + jf * 32 + bSeg);
                uint32_t bvh0[2] = {rv[0], rv[1]}, bvh1[2] = {rv[2], rv[3]};
                uint32_t bvl0[2] = {rl[0], rl[1]}, bvl1[2] = {rl[2], rl[3]};
                mma_bf16(o[pr * 2], aph, bvh0);
                mma_bf16(o[pr * 2], aph, bvl0);
                mma_bf16(o[pr * 2], apl, bvh0);
                mma_bf16(o[pr * 2 + 1], aph, bvh1);
                mma_bf16(o[pr * 2 + 1], aph, bvl1);
                mma_bf16(o[pr * 2 + 1], apl, bvh1);
            }
        }
    }

    const float inv0 = 1.f / l0v;
    const float inv1 = 1.f / l1v;
    const int r0 = lane >> 2;
    const int c2 = (lane & 3) * 2;
    float* O0 = Out + (qrow0 + w * 16 + r0) * D + h * 64;
#pragma unroll
    for (int nf = 0; nf < 8; ++nf) {
        *(float2*)(O0 + nf * 8 + c2) =
            make_float2(o[nf][0] * inv0, o[nf][1] * inv0);
        *(float2*)(O0 + (size_t)8 * D + nf * 8 + c2) =
            make_float2(o[nf][2] * inv1, o[nf][3] * inv1);
    }
}

// ----------------------------------------------------------------------------
// Launch
// ----------------------------------------------------------------------------
extern "C" void kernel_launch(void* const* d_in, const int* in_sizes, int n_in,
                              void* d_out, int out_size)
{
    const float* x[3] = {(const float*)d_in[0], (const float*)d_in[1],
                         (const float*)d_in[2]};
    const float* w[3] = {(const float*)d_in[3], (const float*)d_in[4],
                         (const float*)d_in[5]};
    float* out = (float*)d_out;

    const int D = MHA_D, M = MHA_M, S = MHA_S, H = MHA_H;
    const int B = M / S;

    __nv_bfloat16 *Qhi, *Qlo, *Khi, *Klo, *Vhi, *Vlo, *Bhi, *Blo;
    cudaGetSymbolAddress((void**)&Qhi, g_Qhi);
    cudaGetSymbolAddress((void**)&Qlo, g_Qlo);
    cudaGetSymbolAddress((void**)&Khi, g_Khi);
    cudaGetSymbolAddress((void**)&Klo, g_Klo);
    cudaGetSymbolAddress((void**)&Vhi, g_Vhi);
    cudaGetSymbolAddress((void**)&Vlo, g_Vlo);
    cudaGetSymbolAddress((void**)&Bhi, g_Bhi);
    cudaGetSymbolAddress((void**)&Blo, g_Blo);

    __nv_bfloat16* outs_hi[3] = {Qhi, Khi, Vhi};
    __nv_bfloat16* outs_lo[3] = {Qlo, Klo, Vlo};

    cudaFuncSetAttribute(gemm_fused,
                         cudaFuncAttributeMaxDynamicSharedMemorySize, GEMM_SMEM);
    cudaFuncSetAttribute(flash_mma,
                         cudaFuncAttributeMaxDynamicSharedMemorySize, FM_SMEM);

    for (int p = 0; p < 3; ++p) {
        transpose_split<<<dim3(D / 32, D / 32), dim3(32, 8)>>>(w[p], Bhi, Blo, D);
        gemm_fused<<<dim3(D / 128, M / 128), 128, GEMM_SMEM>>>(
            x[p], Bhi, Blo, outs_hi[p], outs_lo[p], D, D);
    }

    dim3 fg(S / 128, B * H);
    flash_mma<<<fg, 256, FM_SMEM>>>(Qhi, Qlo, Khi, Klo, Vhi, Vlo, out, S, H);
}